// round 2
// baseline (speedup 1.0000x reference)
#include <cuda_runtime.h>

// ---------------------------------------------------------------------------
// 2-layer LSTM, B=2048, T=2048, I=1, H=16.
// TWO batch elements per warp sharing register-resident weights (96 regs).
// Each lane owns 2 gates (A/B) per batch => 4 independent fma2 chains per
// phase, doubling ILP vs R1. Hidden state broadcast via 64B SMEM per (warp,
// layer, batch). fma.rn.f32x2 packed math throughout.
// ---------------------------------------------------------------------------

static constexpr int B = 2048;
static constexpr int T = 2048;
static constexpr int H = 16;

#define L2E 1.4426950408889634f

static __device__ __forceinline__ unsigned long long fma2(unsigned long long a,
                                                          unsigned long long b,
                                                          unsigned long long c) {
    unsigned long long d;
    asm("fma.rn.f32x2 %0, %1, %2, %3;" : "=l"(d) : "l"(a), "l"(b), "l"(c));
    return d;
}
static __device__ __forceinline__ unsigned long long pk2(float a, float b) {
    unsigned long long r;
    asm("mov.b64 %0, {%1, %2};" : "=l"(r) : "f"(a), "f"(b));
    return r;
}
static __device__ __forceinline__ void unpk2(unsigned long long v, float& a, float& b) {
    asm("mov.b64 {%0, %1}, %2;" : "=f"(a), "=f"(b) : "l"(v));
}
static __device__ __forceinline__ float ex2f_(float x) {
    float r; asm("ex2.approx.f32 %0, %1;" : "=f"(r) : "f"(x)); return r;
}
static __device__ __forceinline__ float rcpf_(float x) {
    float r; asm("rcp.approx.f32 %0, %1;" : "=f"(r) : "f"(x)); return r;
}
static __device__ __forceinline__ float sig_(float x) {
    return rcpf_(1.0f + ex2f_(x * (-L2E)));
}
static __device__ __forceinline__ float tanh_(float x) {
    return fmaf(2.0f, rcpf_(1.0f + ex2f_(x * (-2.0f * L2E))), -1.0f);
}

__global__ __launch_bounds__(64, 4)
void lstm2_kernel(const float* __restrict__ x,
                  const float* __restrict__ h0in,
                  const float* __restrict__ c0in,
                  const float* __restrict__ Wih0,
                  const float* __restrict__ Whh0,
                  const float* __restrict__ bih0,
                  const float* __restrict__ bhh0,
                  const float* __restrict__ Wih1,
                  const float* __restrict__ Whh1,
                  const float* __restrict__ bih1,
                  const float* __restrict__ bhh1,
                  float* __restrict__ out)
{
    // [warp][layer][batch-in-warp][16]
    __shared__ __align__(16) float smh[2][2][2][16];

    const int tid  = threadIdx.x;
    const int wid  = tid >> 5;
    const int lane = tid & 31;
    const int j    = lane & 15;
    const int half = lane >> 4;
    const int b0   = blockIdx.x * 4 + wid * 2;   // this warp: batches b0, b0+1

    const int gA = half * 32 + j;   // i[j] (half0) or g[j] (half1)
    const int gB = gA + 16;         // f[j] (half0) or o[j] (half1)

    // ---- register-resident weights, shared by both batches ----
    unsigned long long w0A[8], w0B[8], wiA[8], wiB[8], w1A[8], w1B[8];
    const float2* Wh0v = reinterpret_cast<const float2*>(Whh0);
    const float2* Wi1v = reinterpret_cast<const float2*>(Wih1);
    const float2* Wh1v = reinterpret_cast<const float2*>(Whh1);
#pragma unroll
    for (int p = 0; p < 8; ++p) {
        float2 a  = Wh0v[gA * 8 + p]; w0A[p] = pk2(a.x, a.y);
        float2 b2 = Wh0v[gB * 8 + p]; w0B[p] = pk2(b2.x, b2.y);
        float2 c  = Wi1v[gA * 8 + p]; wiA[p] = pk2(c.x, c.y);
        float2 d  = Wi1v[gB * 8 + p]; wiB[p] = pk2(d.x, d.y);
        float2 e  = Wh1v[gA * 8 + p]; w1A[p] = pk2(e.x, e.y);
        float2 f  = Wh1v[gB * 8 + p]; w1B[p] = pk2(f.x, f.y);
    }
    const float biasA0 = bih0[gA] + bhh0[gA];
    const float biasB0 = bih0[gB] + bhh0[gB];
    const float biasA1 = bih1[gA] + bhh1[gA];
    const float biasB1 = bih1[gB] + bhh1[gB];
    const float wxA = Wih0[gA];     // I == 1
    const float wxB = Wih0[gB];
    const unsigned long long ONE2 = pk2(1.0f, 1.0f);

    // activation params for chain A (half0: sigmoid, half1: tanh)
    const float kA  = half ? (-2.0f * L2E) : (-L2E);
    const float mA  = half ? 2.0f : 1.0f;
    const float cAc = half ? -1.0f : 0.0f;

    // ---- per-batch state ----
    float c0v[2], c1v[2], h0v[2], h1v[2];
#pragma unroll
    for (int n = 0; n < 2; ++n) {
        const int b = b0 + n;
        c0v[n] = c0in[b * H + j];
        c1v[n] = c0in[B * H + b * H + j];
        h0v[n] = h0in[b * H + j];
        h1v[n] = h0in[B * H + b * H + j];
        if (!half) {
            smh[wid][0][n][j] = h0v[n];
            smh[wid][1][n][j] = h1v[n];
        }
    }
    __syncwarp();

    const float* xrow[2];
    float*       orow[2];
    float        xv[2];
#pragma unroll
    for (int n = 0; n < 2; ++n) {
        xrow[n] = x + (size_t)(b0 + n) * T;
        orow[n] = out + (size_t)(b0 + n) * T * H + j;
        xv[n]   = __ldg(xrow[n]);
    }

    for (int t = 0; t < T; ++t) {
        const int tn = (t + 1 < T) ? (t + 1) : (T - 1);
        float xn[2];
#pragma unroll
        for (int n = 0; n < 2; ++n) xn[n] = __ldg(xrow[n] + tn);

        // ============== layer 0, both batches (independent chains) =========
#pragma unroll
        for (int n = 0; n < 2; ++n) {
            const ulonglong2* hp = reinterpret_cast<const ulonglong2*>(smh[wid][0][n]);
            ulonglong2 u0 = hp[0], u1 = hp[1], u2 = hp[2], u3 = hp[3];
            unsigned long long aA = 0ull, aB = 0ull, aA2 = 0ull, aB2 = 0ull;
            aA  = fma2(w0A[0], u0.x, aA);   aB  = fma2(w0B[0], u0.x, aB);
            aA  = fma2(w0A[1], u0.y, aA);   aB  = fma2(w0B[1], u0.y, aB);
            aA  = fma2(w0A[2], u1.x, aA);   aB  = fma2(w0B[2], u1.x, aB);
            aA  = fma2(w0A[3], u1.y, aA);   aB  = fma2(w0B[3], u1.y, aB);
            aA2 = fma2(w0A[4], u2.x, aA2);  aB2 = fma2(w0B[4], u2.x, aB2);
            aA2 = fma2(w0A[5], u2.y, aA2);  aB2 = fma2(w0B[5], u2.y, aB2);
            aA2 = fma2(w0A[6], u3.x, aA2);  aB2 = fma2(w0B[6], u3.x, aB2);
            aA2 = fma2(w0A[7], u3.y, aA2);  aB2 = fma2(w0B[7], u3.y, aB2);
            aA  = fma2(aA2, ONE2, aA);      aB  = fma2(aB2, ONE2, aB);

            float aL, aH, bL, bH;
            unpk2(aA, aL, aH);
            unpk2(aB, bL, bH);
            const float gAraw = (aL + aH) + fmaf(xv[n], wxA, biasA0);
            const float gBraw = (bL + bH) + fmaf(xv[n], wxB, biasB0);

            const float sA = fmaf(mA, rcpf_(1.0f + ex2f_(gAraw * kA)), cAc);
            const float sB = sig_(gBraw);

            const float gg = __shfl_xor_sync(0xffffffffu, sA, 16);
            const float oo = __shfl_xor_sync(0xffffffffu, sB, 16);
            c0v[n] = fmaf(sB, c0v[n], sA * gg);      // half0 authoritative
            h0v[n] = oo * tanh_(c0v[n]);
            if (!half) smh[wid][0][n][j] = h0v[n];
        }
        __syncwarp();

        // ============== layer 1, both batches ==============================
#pragma unroll
        for (int n = 0; n < 2; ++n) {
            const ulonglong2* hp0 = reinterpret_cast<const ulonglong2*>(smh[wid][0][n]);
            const ulonglong2* hp1 = reinterpret_cast<const ulonglong2*>(smh[wid][1][n]);
            ulonglong2 u0 = hp0[0], u1 = hp0[1], u2 = hp0[2], u3 = hp0[3];
            ulonglong2 v0 = hp1[0], v1 = hp1[1], v2 = hp1[2], v3 = hp1[3];
            unsigned long long uA = 0ull, uB = 0ull, vA = 0ull, vB = 0ull;
            uA = fma2(wiA[0], u0.x, uA);  uB = fma2(wiB[0], u0.x, uB);
            uA = fma2(wiA[1], u0.y, uA);  uB = fma2(wiB[1], u0.y, uB);
            uA = fma2(wiA[2], u1.x, uA);  uB = fma2(wiB[2], u1.x, uB);
            uA = fma2(wiA[3], u1.y, uA);  uB = fma2(wiB[3], u1.y, uB);
            uA = fma2(wiA[4], u2.x, uA);  uB = fma2(wiB[4], u2.x, uB);
            uA = fma2(wiA[5], u2.y, uA);  uB = fma2(wiB[5], u2.y, uB);
            uA = fma2(wiA[6], u3.x, uA);  uB = fma2(wiB[6], u3.x, uB);
            uA = fma2(wiA[7], u3.y, uA);  uB = fma2(wiB[7], u3.y, uB);

            vA = fma2(w1A[0], v0.x, vA);  vB = fma2(w1B[0], v0.x, vB);
            vA = fma2(w1A[1], v0.y, vA);  vB = fma2(w1B[1], v0.y, vB);
            vA = fma2(w1A[2], v1.x, vA);  vB = fma2(w1B[2], v1.x, vB);
            vA = fma2(w1A[3], v1.y, vA);  vB = fma2(w1B[3], v1.y, vB);
            vA = fma2(w1A[4], v2.x, vA);  vB = fma2(w1B[4], v2.x, vB);
            vA = fma2(w1A[5], v2.y, vA);  vB = fma2(w1B[5], v2.y, vB);
            vA = fma2(w1A[6], v3.x, vA);  vB = fma2(w1B[6], v3.x, vB);
            vA = fma2(w1A[7], v3.y, vA);  vB = fma2(w1B[7], v3.y, vB);

            const unsigned long long aA = fma2(vA, ONE2, uA);
            const unsigned long long aB = fma2(vB, ONE2, uB);

            float aL, aH, bL, bH;
            unpk2(aA, aL, aH);
            unpk2(aB, bL, bH);
            const float gAraw = (aL + aH) + biasA1;
            const float gBraw = (bL + bH) + biasB1;

            const float sA = fmaf(mA, rcpf_(1.0f + ex2f_(gAraw * kA)), cAc);
            const float sB = sig_(gBraw);

            const float gg = __shfl_xor_sync(0xffffffffu, sA, 16);
            const float oo = __shfl_xor_sync(0xffffffffu, sB, 16);
            c1v[n] = fmaf(sB, c1v[n], sA * gg);
            h1v[n] = oo * tanh_(c1v[n]);
            if (!half) {
                smh[wid][1][n][j] = h1v[n];
                orow[n][(size_t)t * H] = h1v[n];
            }
        }
#pragma unroll
        for (int n = 0; n < 2; ++n) xv[n] = xn[n];
        __syncwarp();
    }

    // final states: hN [2,B,H] then cN [2,B,H] appended after out1 [B,T,H]
    if (!half) {
#pragma unroll
        for (int n = 0; n < 2; ++n) {
            const int b = b0 + n;
            float* hN = out + (size_t)B * T * H;
            float* cN = hN + 2 * B * H;
            hN[b * H + j]         = h0v[n];
            hN[B * H + b * H + j] = h1v[n];
            cN[b * H + j]         = c0v[n];
            cN[B * H + b * H + j] = c1v[n];
        }
    }
}

extern "C" void kernel_launch(void* const* d_in, const int* in_sizes, int n_in,
                              void* d_out, int out_size) {
    const float* x    = (const float*)d_in[0];
    const float* h0   = (const float*)d_in[1];
    const float* c0   = (const float*)d_in[2];
    const float* Wih0 = (const float*)d_in[3];
    const float* Whh0 = (const float*)d_in[4];
    const float* bih0 = (const float*)d_in[5];
    const float* bhh0 = (const float*)d_in[6];
    const float* Wih1 = (const float*)d_in[7];
    const float* Whh1 = (const float*)d_in[8];
    const float* bih1 = (const float*)d_in[9];
    const float* bhh1 = (const float*)d_in[10];
    float* out = (float*)d_out;

    lstm2_kernel<<<B / 4, 64>>>(x, h0, c0, Wih0, Whh0, bih0, bhh0,
                                Wih1, Whh1, bih1, bhh1, out);
}

// round 3
// speedup vs baseline: 1.2994x; 1.2994x over previous
#include <cuda_runtime.h>

// ---------------------------------------------------------------------------
// 2-layer LSTM, B=2048, T=2048, I=1, H=16.
// One warp per batch (R1 occupancy), but the two layers are SOFTWARE
// PIPELINED: superstep s computes layer0 step s+1 (chain P) and layer1 step s
// (chain Q) concurrently — both depend only on h0(s), so the two ~190-cycle
// dependency chains overlap instead of serializing.
// Weights register-resident, fma.rn.f32x2 packed math, h via 64B SMEM.
// ---------------------------------------------------------------------------

static constexpr int B = 2048;
static constexpr int T = 2048;
static constexpr int H = 16;

#define L2E 1.4426950408889634f

static __device__ __forceinline__ unsigned long long fma2(unsigned long long a,
                                                          unsigned long long b,
                                                          unsigned long long c) {
    unsigned long long d;
    asm("fma.rn.f32x2 %0, %1, %2, %3;" : "=l"(d) : "l"(a), "l"(b), "l"(c));
    return d;
}
static __device__ __forceinline__ unsigned long long pk2(float a, float b) {
    unsigned long long r;
    asm("mov.b64 %0, {%1, %2};" : "=l"(r) : "f"(a), "f"(b));
    return r;
}
static __device__ __forceinline__ void unpk2(unsigned long long v, float& a, float& b) {
    asm("mov.b64 {%0, %1}, %2;" : "=f"(a), "=f"(b) : "l"(v));
}
static __device__ __forceinline__ float ex2f_(float x) {
    float r; asm("ex2.approx.f32 %0, %1;" : "=f"(r) : "f"(x)); return r;
}
static __device__ __forceinline__ float rcpf_(float x) {
    float r; asm("rcp.approx.f32 %0, %1;" : "=f"(r) : "f"(x)); return r;
}
static __device__ __forceinline__ float sig_(float x) {
    return rcpf_(1.0f + ex2f_(x * (-L2E)));
}
static __device__ __forceinline__ float tanh_(float x) {
    return fmaf(2.0f, rcpf_(1.0f + ex2f_(x * (-2.0f * L2E))), -1.0f);
}

__global__ __launch_bounds__(64, 7)
void lstm2_kernel(const float* __restrict__ x,
                  const float* __restrict__ h0in,
                  const float* __restrict__ c0in,
                  const float* __restrict__ Wih0,
                  const float* __restrict__ Whh0,
                  const float* __restrict__ bih0,
                  const float* __restrict__ bhh0,
                  const float* __restrict__ Wih1,
                  const float* __restrict__ Whh1,
                  const float* __restrict__ bih1,
                  const float* __restrict__ bhh1,
                  float* __restrict__ out)
{
    __shared__ __align__(16) float smh[2][2][16];   // [warp][layer][16]

    const int tid  = threadIdx.x;
    const int wid  = tid >> 5;
    const int lane = tid & 31;
    const int j    = lane & 15;
    const int half = lane >> 4;
    const int b    = blockIdx.x * 2 + wid;

    const int gA = half * 32 + j;   // i[j] (half0) or g[j] (half1)
    const int gB = gA + 16;         // f[j] (half0) or o[j] (half1)

    // ---- register-resident weights ----
    unsigned long long w0A[8], w0B[8], wiA[8], wiB[8], w1A[8], w1B[8];
    const float2* Wh0v = reinterpret_cast<const float2*>(Whh0);
    const float2* Wi1v = reinterpret_cast<const float2*>(Wih1);
    const float2* Wh1v = reinterpret_cast<const float2*>(Whh1);
#pragma unroll
    for (int p = 0; p < 8; ++p) {
        float2 a  = Wh0v[gA * 8 + p]; w0A[p] = pk2(a.x, a.y);
        float2 b2 = Wh0v[gB * 8 + p]; w0B[p] = pk2(b2.x, b2.y);
        float2 c  = Wi1v[gA * 8 + p]; wiA[p] = pk2(c.x, c.y);
        float2 d  = Wi1v[gB * 8 + p]; wiB[p] = pk2(d.x, d.y);
        float2 e  = Wh1v[gA * 8 + p]; w1A[p] = pk2(e.x, e.y);
        float2 f  = Wh1v[gB * 8 + p]; w1B[p] = pk2(f.x, f.y);
    }
    const float biasA0 = bih0[gA] + bhh0[gA];
    const float biasB0 = bih0[gB] + bhh0[gB];
    const float biasA1 = bih1[gA] + bhh1[gA];
    const float biasB1 = bih1[gB] + bhh1[gB];
    const float wxA = Wih0[gA];     // I == 1
    const float wxB = Wih0[gB];
    const unsigned long long ONE2 = pk2(1.0f, 1.0f);

    // activation params for chain-A scalar (half0: sigmoid, half1: tanh)
    const float kA  = half ? (-2.0f * L2E) : (-L2E);
    const float mA  = half ? 2.0f : 1.0f;
    const float cAc = half ? -1.0f : 0.0f;

    // ---- state (half0 lanes authoritative) ----
    float c0v = c0in[b * H + j];
    float c1v = c0in[B * H + b * H + j];
    float h0v = h0in[b * H + j];
    float h1v = h0in[B * H + b * H + j];

    float* h0s = smh[wid][0];
    float* h1s = smh[wid][1];
    if (!half) { h0s[j] = h0v; h1s[j] = h1v; }
    __syncwarp();

    const float* xrow = x + (size_t)b * T;
    float*       orow = out + (size_t)b * T * H + j;

    // ======================= prologue: layer0 step 0 =======================
    {
        const float xv0 = __ldg(xrow);
        const ulonglong2* hp = reinterpret_cast<const ulonglong2*>(h0s);
        ulonglong2 u0 = hp[0], u1 = hp[1], u2 = hp[2], u3 = hp[3];
        __syncwarp();
        unsigned long long aA = 0ull, aB = 0ull, aA2 = 0ull, aB2 = 0ull;
        aA  = fma2(w0A[0], u0.x, aA);   aB  = fma2(w0B[0], u0.x, aB);
        aA  = fma2(w0A[1], u0.y, aA);   aB  = fma2(w0B[1], u0.y, aB);
        aA  = fma2(w0A[2], u1.x, aA);   aB  = fma2(w0B[2], u1.x, aB);
        aA  = fma2(w0A[3], u1.y, aA);   aB  = fma2(w0B[3], u1.y, aB);
        aA2 = fma2(w0A[4], u2.x, aA2);  aB2 = fma2(w0B[4], u2.x, aB2);
        aA2 = fma2(w0A[5], u2.y, aA2);  aB2 = fma2(w0B[5], u2.y, aB2);
        aA2 = fma2(w0A[6], u3.x, aA2);  aB2 = fma2(w0B[6], u3.x, aB2);
        aA2 = fma2(w0A[7], u3.y, aA2);  aB2 = fma2(w0B[7], u3.y, aB2);
        aA  = fma2(aA2, ONE2, aA);      aB  = fma2(aB2, ONE2, aB);
        float aL, aH, bL, bH;
        unpk2(aA, aL, aH); unpk2(aB, bL, bH);
        const float gAraw = (aL + aH) + fmaf(xv0, wxA, biasA0);
        const float gBraw = (bL + bH) + fmaf(xv0, wxB, biasB0);
        const float sA = fmaf(mA, rcpf_(1.0f + ex2f_(gAraw * kA)), cAc);
        const float sB = sig_(gBraw);
        const float gg = __shfl_xor_sync(0xffffffffu, sA, 16);
        const float oo = __shfl_xor_sync(0xffffffffu, sB, 16);
        c0v = fmaf(sB, c0v, sA * gg);
        h0v = oo * tanh_(c0v);
        if (!half) h0s[j] = h0v;
        __syncwarp();
    }

    float xv = __ldg(xrow + 1);   // x for layer0 step 1 (superstep 0)

    // ================= supersteps s = 0 .. T-2 =============================
    // chain P: layer0 step s+1 (from h0s = h0[s], xv = x[s+1])
    // chain Q: layer1 step s   (from h0s = h0[s], h1s = h1[s-1])
    for (int s = 0; s < T - 1; ++s) {
        const ulonglong2* hp0 = reinterpret_cast<const ulonglong2*>(h0s);
        const ulonglong2* hp1 = reinterpret_cast<const ulonglong2*>(h1s);
        ulonglong2 u0 = hp0[0], u1 = hp0[1], u2 = hp0[2], u3 = hp0[3];
        ulonglong2 v0 = hp1[0], v1 = hp1[1], v2 = hp1[2], v3 = hp1[3];
        __syncwarp();

        const int xi = (s + 2 < T) ? (s + 2) : (T - 1);
        const float xnext = __ldg(xrow + xi);

        // ---- P accumulation (4 subchains of depth 4) ----
        unsigned long long pA = 0ull, pB = 0ull, pA2 = 0ull, pB2 = 0ull;
        pA  = fma2(w0A[0], u0.x, pA);   pB  = fma2(w0B[0], u0.x, pB);
        pA  = fma2(w0A[1], u0.y, pA);   pB  = fma2(w0B[1], u0.y, pB);
        pA  = fma2(w0A[2], u1.x, pA);   pB  = fma2(w0B[2], u1.x, pB);
        pA  = fma2(w0A[3], u1.y, pA);   pB  = fma2(w0B[3], u1.y, pB);
        pA2 = fma2(w0A[4], u2.x, pA2);  pB2 = fma2(w0B[4], u2.x, pB2);
        pA2 = fma2(w0A[5], u2.y, pA2);  pB2 = fma2(w0B[5], u2.y, pB2);
        pA2 = fma2(w0A[6], u3.x, pA2);  pB2 = fma2(w0B[6], u3.x, pB2);
        pA2 = fma2(w0A[7], u3.y, pA2);  pB2 = fma2(w0B[7], u3.y, pB2);

        // ---- Q accumulation (4 subchains of depth 8) ----
        unsigned long long qUA = 0ull, qUB = 0ull, qVA = 0ull, qVB = 0ull;
        qUA = fma2(wiA[0], u0.x, qUA);  qUB = fma2(wiB[0], u0.x, qUB);
        qVA = fma2(w1A[0], v0.x, qVA);  qVB = fma2(w1B[0], v0.x, qVB);
        qUA = fma2(wiA[1], u0.y, qUA);  qUB = fma2(wiB[1], u0.y, qUB);
        qVA = fma2(w1A[1], v0.y, qVA);  qVB = fma2(w1B[1], v0.y, qVB);
        qUA = fma2(wiA[2], u1.x, qUA);  qUB = fma2(wiB[2], u1.x, qUB);
        qVA = fma2(w1A[2], v1.x, qVA);  qVB = fma2(w1B[2], v1.x, qVB);
        qUA = fma2(wiA[3], u1.y, qUA);  qUB = fma2(wiB[3], u1.y, qUB);
        qVA = fma2(w1A[3], v1.y, qVA);  qVB = fma2(w1B[3], v1.y, qVB);
        qUA = fma2(wiA[4], u2.x, qUA);  qUB = fma2(wiB[4], u2.x, qUB);
        qVA = fma2(w1A[4], v2.x, qVA);  qVB = fma2(w1B[4], v2.x, qVB);
        qUA = fma2(wiA[5], u2.y, qUA);  qUB = fma2(wiB[5], u2.y, qUB);
        qVA = fma2(w1A[5], v2.y, qVA);  qVB = fma2(w1B[5], v2.y, qVB);
        qUA = fma2(wiA[6], u3.x, qUA);  qUB = fma2(wiB[6], u3.x, qUB);
        qVA = fma2(w1A[6], v3.x, qVA);  qVB = fma2(w1B[6], v3.x, qVB);
        qUA = fma2(wiA[7], u3.y, qUA);  qUB = fma2(wiB[7], u3.y, qUB);
        qVA = fma2(w1A[7], v3.y, qVA);  qVB = fma2(w1B[7], v3.y, qVB);

        // ---- combine + scalar gates ----
        const unsigned long long paA = fma2(pA2, ONE2, pA);
        const unsigned long long paB = fma2(pB2, ONE2, pB);
        const unsigned long long qaA = fma2(qVA, ONE2, qUA);
        const unsigned long long qaB = fma2(qVB, ONE2, qUB);

        float paL, paH, pbL, pbH, qaL, qaH, qbL, qbH;
        unpk2(paA, paL, paH); unpk2(paB, pbL, pbH);
        unpk2(qaA, qaL, qaH); unpk2(qaB, qbL, qbH);
        const float pAraw = (paL + paH) + fmaf(xv, wxA, biasA0);
        const float pBraw = (pbL + pbH) + fmaf(xv, wxB, biasB0);
        const float qAraw = (qaL + qaH) + biasA1;
        const float qBraw = (qbL + qbH) + biasB1;

        // ---- activations (both chains' MUFUs interleavable) ----
        const float psA = fmaf(mA, rcpf_(1.0f + ex2f_(pAraw * kA)), cAc);
        const float qsA = fmaf(mA, rcpf_(1.0f + ex2f_(qAraw * kA)), cAc);
        const float psB = sig_(pBraw);
        const float qsB = sig_(qBraw);

        // ---- cross-half exchange ----
        const float pgg = __shfl_xor_sync(0xffffffffu, psA, 16);
        const float qgg = __shfl_xor_sync(0xffffffffu, qsA, 16);
        const float poo = __shfl_xor_sync(0xffffffffu, psB, 16);
        const float qoo = __shfl_xor_sync(0xffffffffu, qsB, 16);

        // ---- state updates (half0 authoritative) ----
        c0v = fmaf(psB, c0v, psA * pgg);
        c1v = fmaf(qsB, c1v, qsA * qgg);
        h0v = poo * tanh_(c0v);
        h1v = qoo * tanh_(c1v);

        if (!half) {
            h0s[j] = h0v;
            h1s[j] = h1v;
            orow[(size_t)s * H] = h1v;      // out1[b, s, j]
        }
        xv = xnext;
        __syncwarp();
    }

    // =================== tail superstep: layer1 step T-1 ===================
    {
        const ulonglong2* hp0 = reinterpret_cast<const ulonglong2*>(h0s);
        const ulonglong2* hp1 = reinterpret_cast<const ulonglong2*>(h1s);
        ulonglong2 u0 = hp0[0], u1 = hp0[1], u2 = hp0[2], u3 = hp0[3];
        ulonglong2 v0 = hp1[0], v1 = hp1[1], v2 = hp1[2], v3 = hp1[3];
        __syncwarp();
        unsigned long long qUA = 0ull, qUB = 0ull, qVA = 0ull, qVB = 0ull;
        qUA = fma2(wiA[0], u0.x, qUA);  qUB = fma2(wiB[0], u0.x, qUB);
        qVA = fma2(w1A[0], v0.x, qVA);  qVB = fma2(w1B[0], v0.x, qVB);
        qUA = fma2(wiA[1], u0.y, qUA);  qUB = fma2(wiB[1], u0.y, qUB);
        qVA = fma2(w1A[1], v0.y, qVA);  qVB = fma2(w1B[1], v0.y, qVB);
        qUA = fma2(wiA[2], u1.x, qUA);  qUB = fma2(wiB[2], u1.x, qUB);
        qVA = fma2(w1A[2], v1.x, qVA);  qVB = fma2(w1B[2], v1.x, qVB);
        qUA = fma2(wiA[3], u1.y, qUA);  qUB = fma2(wiB[3], u1.y, qUB);
        qVA = fma2(w1A[3], v1.y, qVA);  qVB = fma2(w1B[3], v1.y, qVB);
        qUA = fma2(wiA[4], u2.x, qUA);  qUB = fma2(wiB[4], u2.x, qUB);
        qVA = fma2(w1A[4], v2.x, qVA);  qVB = fma2(w1B[4], v2.x, qVB);
        qUA = fma2(wiA[5], u2.y, qUA);  qUB = fma2(wiB[5], u2.y, qUB);
        qVA = fma2(w1A[5], v2.y, qVA);  qVB = fma2(w1B[5], v2.y, qVB);
        qUA = fma2(wiA[6], u3.x, qUA);  qUB = fma2(wiB[6], u3.x, qUB);
        qVA = fma2(w1A[6], v3.x, qVA);  qVB = fma2(w1B[6], v3.x, qVB);
        qUA = fma2(wiA[7], u3.y, qUA);  qUB = fma2(wiB[7], u3.y, qUB);
        qVA = fma2(w1A[7], v3.y, qVA);  qVB = fma2(w1B[7], v3.y, qVB);
        const unsigned long long qaA = fma2(qVA, ONE2, qUA);
        const unsigned long long qaB = fma2(qVB, ONE2, qUB);
        float qaL, qaH, qbL, qbH;
        unpk2(qaA, qaL, qaH); unpk2(qaB, qbL, qbH);
        const float qAraw = (qaL + qaH) + biasA1;
        const float qBraw = (qbL + qbH) + biasB1;
        const float qsA = fmaf(mA, rcpf_(1.0f + ex2f_(qAraw * kA)), cAc);
        const float qsB = sig_(qBraw);
        const float qgg = __shfl_xor_sync(0xffffffffu, qsA, 16);
        const float qoo = __shfl_xor_sync(0xffffffffu, qsB, 16);
        c1v = fmaf(qsB, c1v, qsA * qgg);
        h1v = qoo * tanh_(c1v);
        if (!half) orow[(size_t)(T - 1) * H] = h1v;
    }

    // final states: hN [2,B,H] then cN [2,B,H] appended after out1 [B,T,H]
    if (!half) {
        float* hN = out + (size_t)B * T * H;
        float* cN = hN + 2 * B * H;
        hN[b * H + j]         = h0v;
        hN[B * H + b * H + j] = h1v;
        cN[b * H + j]         = c0v;
        cN[B * H + b * H + j] = c1v;
    }
}

extern "C" void kernel_launch(void* const* d_in, const int* in_sizes, int n_in,
                              void* d_out, int out_size) {
    const float* x    = (const float*)d_in[0];
    const float* h0   = (const float*)d_in[1];
    const float* c0   = (const float*)d_in[2];
    const float* Wih0 = (const float*)d_in[3];
    const float* Whh0 = (const float*)d_in[4];
    const float* bih0 = (const float*)d_in[5];
    const float* bhh0 = (const float*)d_in[6];
    const float* Wih1 = (const float*)d_in[7];
    const float* Whh1 = (const float*)d_in[8];
    const float* bih1 = (const float*)d_in[9];
    const float* bhh1 = (const float*)d_in[10];
    float* out = (float*)d_out;

    lstm2_kernel<<<B / 2, 64>>>(x, h0, c0, Wih0, Whh0, bih0, bhh0,
                                Wih1, Whh1, bih1, bhh1, out);
}

// round 4
// speedup vs baseline: 1.5853x; 1.2201x over previous
#include <cuda_runtime.h>

// ---------------------------------------------------------------------------
// 2-layer LSTM, B=2048, T=2048, I=1, H=16.
// One warp per batch; layer0(s+1) and layer1(s) software-pipelined.
// R4: all activations via MUFU.TANH (tanh.approx.f32), double-buffered SMEM
// h-exchange (1 syncwarp/superstep), biases folded into packed accum init.
// ---------------------------------------------------------------------------

static constexpr int B = 2048;
static constexpr int T = 2048;
static constexpr int H = 16;

static __device__ __forceinline__ unsigned long long fma2(unsigned long long a,
                                                          unsigned long long b,
                                                          unsigned long long c) {
    unsigned long long d;
    asm("fma.rn.f32x2 %0, %1, %2, %3;" : "=l"(d) : "l"(a), "l"(b), "l"(c));
    return d;
}
static __device__ __forceinline__ unsigned long long pk2(float a, float b) {
    unsigned long long r;
    asm("mov.b64 %0, {%1, %2};" : "=l"(r) : "f"(a), "f"(b));
    return r;
}
static __device__ __forceinline__ void unpk2(unsigned long long v, float& a, float& b) {
    asm("mov.b64 {%0, %1}, %2;" : "=f"(a), "=f"(b) : "l"(v));
}
static __device__ __forceinline__ float tanhA(float x) {
    float r; asm("tanh.approx.f32 %0, %1;" : "=f"(r) : "f"(x)); return r;
}
// sigmoid(x) = 0.5*tanh(0.5x) + 0.5
static __device__ __forceinline__ float sigA(float x) {
    return fmaf(0.5f, tanhA(0.5f * x), 0.5f);
}

__global__ __launch_bounds__(64, 7)
void lstm2_kernel(const float* __restrict__ x,
                  const float* __restrict__ h0in,
                  const float* __restrict__ c0in,
                  const float* __restrict__ Wih0,
                  const float* __restrict__ Whh0,
                  const float* __restrict__ bih0,
                  const float* __restrict__ bhh0,
                  const float* __restrict__ Wih1,
                  const float* __restrict__ Whh1,
                  const float* __restrict__ bih1,
                  const float* __restrict__ bhh1,
                  float* __restrict__ out)
{
    // [warp][buffer][32 floats: layer0 h at 0..15, layer1 h at 16..31]
    __shared__ __align__(16) float smh[2][2][32];

    const int tid  = threadIdx.x;
    const int wid  = tid >> 5;
    const int lane = tid & 31;
    const int j    = lane & 15;
    const int half = lane >> 4;
    const int b    = blockIdx.x * 2 + wid;

    const int gA = half * 32 + j;   // i[j] (half0) or g[j] (half1)
    const int gB = gA + 16;         // f[j] (half0) or o[j] (half1)

    // ---- register-resident weights ----
    unsigned long long w0A[8], w0B[8], wiA[8], wiB[8], w1A[8], w1B[8];
    const float2* Wh0v = reinterpret_cast<const float2*>(Whh0);
    const float2* Wi1v = reinterpret_cast<const float2*>(Wih1);
    const float2* Wh1v = reinterpret_cast<const float2*>(Whh1);
#pragma unroll
    for (int p = 0; p < 8; ++p) {
        float2 a  = Wh0v[gA * 8 + p]; w0A[p] = pk2(a.x, a.y);
        float2 b2 = Wh0v[gB * 8 + p]; w0B[p] = pk2(b2.x, b2.y);
        float2 c  = Wi1v[gA * 8 + p]; wiA[p] = pk2(c.x, c.y);
        float2 d  = Wi1v[gB * 8 + p]; wiB[p] = pk2(d.x, d.y);
        float2 e  = Wh1v[gA * 8 + p]; w1A[p] = pk2(e.x, e.y);
        float2 f  = Wh1v[gB * 8 + p]; w1B[p] = pk2(f.x, f.y);
    }
    // biases folded into packed accumulator inits
    const unsigned long long bias2A0 = pk2(bih0[gA] + bhh0[gA], 0.0f);
    const unsigned long long bias2B0 = pk2(bih0[gB] + bhh0[gB], 0.0f);
    const unsigned long long bias2A1 = pk2(bih1[gA] + bhh1[gA], 0.0f);
    const unsigned long long bias2B1 = pk2(bih1[gB] + bhh1[gB], 0.0f);
    const float wxA = Wih0[gA];     // I == 1
    const float wxB = Wih0[gB];
    const unsigned long long ONE2 = pk2(1.0f, 1.0f);

    // chain-A activation constants: half0 sigmoid (0.5,0.5,0.5), half1 tanh (1,1,0)
    const float kA = half ? 1.0f : 0.5f;
    const float mA = half ? 1.0f : 0.5f;
    const float cA = half ? 0.0f : 0.5f;

    // ---- state (half0 lanes authoritative) ----
    float c0v = c0in[b * H + j];
    float c1v = c0in[B * H + b * H + j];
    float h0v = h0in[b * H + j];
    float h1v = h0in[B * H + b * H + j];

    float* bufA = smh[wid][0];
    float* bufB = smh[wid][1];
    if (!half) { bufA[j] = h0v; bufA[16 + j] = h1v; }
    __syncwarp();

    const float* xrow = x + (size_t)b * T;
    float*       outp = out + (size_t)b * T * H + j;

    // ======================= prologue: layer0 step 0 =======================
    {
        const float xv0 = __ldg(xrow);
        const ulonglong2* hp = reinterpret_cast<const ulonglong2*>(bufA);
        ulonglong2 u0 = hp[0], u1 = hp[1], u2 = hp[2], u3 = hp[3];
        unsigned long long aA = bias2A0, aB = bias2B0, aA2 = 0ull, aB2 = 0ull;
        aA  = fma2(w0A[0], u0.x, aA);   aB  = fma2(w0B[0], u0.x, aB);
        aA  = fma2(w0A[1], u0.y, aA);   aB  = fma2(w0B[1], u0.y, aB);
        aA  = fma2(w0A[2], u1.x, aA);   aB  = fma2(w0B[2], u1.x, aB);
        aA  = fma2(w0A[3], u1.y, aA);   aB  = fma2(w0B[3], u1.y, aB);
        aA2 = fma2(w0A[4], u2.x, aA2);  aB2 = fma2(w0B[4], u2.x, aB2);
        aA2 = fma2(w0A[5], u2.y, aA2);  aB2 = fma2(w0B[5], u2.y, aB2);
        aA2 = fma2(w0A[6], u3.x, aA2);  aB2 = fma2(w0B[6], u3.x, aB2);
        aA2 = fma2(w0A[7], u3.y, aA2);  aB2 = fma2(w0B[7], u3.y, aB2);
        aA  = fma2(aA2, ONE2, aA);      aB  = fma2(aB2, ONE2, aB);
        float aL, aH, bL, bH;
        unpk2(aA, aL, aH); unpk2(aB, bL, bH);
        const float gAraw = fmaf(xv0, wxA, aL + aH);
        const float gBraw = fmaf(xv0, wxB, bL + bH);
        const float sA = fmaf(mA, tanhA(kA * gAraw), cA);
        const float sB = sigA(gBraw);
        const float gg = __shfl_xor_sync(0xffffffffu, sA, 16);
        const float oo = __shfl_xor_sync(0xffffffffu, sB, 16);
        c0v = fmaf(sB, c0v, sA * gg);
        h0v = oo * tanhA(c0v);
        __syncwarp();                 // reads of bufA done before overwrite
        if (!half) bufA[j] = h0v;     // h0(0) -> bufA
        __syncwarp();
    }

    float xv = __ldg(xrow + 1);   // x for layer0 step 1 (superstep 0)

    // superstep s: reads RB = h0(s), h1(s-1); writes WB = h0(s+1), h1(s).
#define SUPERSTEP(RB, WB, SIDX)                                                \
    {                                                                          \
        const ulonglong2* hp0 = reinterpret_cast<const ulonglong2*>(RB);       \
        const ulonglong2* hp1 = reinterpret_cast<const ulonglong2*>((RB) + 16);\
        ulonglong2 u0 = hp0[0], u1 = hp0[1], u2 = hp0[2], u3 = hp0[3];         \
        ulonglong2 v0 = hp1[0], v1 = hp1[1], v2 = hp1[2], v3 = hp1[3];         \
        const float xnext = __ldg(xrow + min((SIDX) + 2, T - 1));              \
        unsigned long long pA = bias2A0, pB = bias2B0, pA2 = 0ull, pB2 = 0ull; \
        pA  = fma2(w0A[0], u0.x, pA);   pB  = fma2(w0B[0], u0.x, pB);          \
        pA  = fma2(w0A[1], u0.y, pA);   pB  = fma2(w0B[1], u0.y, pB);          \
        pA  = fma2(w0A[2], u1.x, pA);   pB  = fma2(w0B[2], u1.x, pB);          \
        pA  = fma2(w0A[3], u1.y, pA);   pB  = fma2(w0B[3], u1.y, pB);          \
        pA2 = fma2(w0A[4], u2.x, pA2);  pB2 = fma2(w0B[4], u2.x, pB2);         \
        pA2 = fma2(w0A[5], u2.y, pA2);  pB2 = fma2(w0B[5], u2.y, pB2);         \
        pA2 = fma2(w0A[6], u3.x, pA2);  pB2 = fma2(w0B[6], u3.x, pB2);         \
        pA2 = fma2(w0A[7], u3.y, pA2);  pB2 = fma2(w0B[7], u3.y, pB2);         \
        unsigned long long qUA = bias2A1, qUB = bias2B1;                       \
        unsigned long long qVA = 0ull,   qVB = 0ull;                           \
        qUA = fma2(wiA[0], u0.x, qUA);  qUB = fma2(wiB[0], u0.x, qUB);         \
        qVA = fma2(w1A[0], v0.x, qVA);  qVB = fma2(w1B[0], v0.x, qVB);         \
        qUA = fma2(wiA[1], u0.y, qUA);  qUB = fma2(wiB[1], u0.y, qUB);         \
        qVA = fma2(w1A[1], v0.y, qVA);  qVB = fma2(w1B[1], v0.y, qVB);         \
        qUA = fma2(wiA[2], u1.x, qUA);  qUB = fma2(wiB[2], u1.x, qUB);         \
        qVA = fma2(w1A[2], v1.x, qVA);  qVB = fma2(w1B[2], v1.x, qVB);         \
        qUA = fma2(wiA[3], u1.y, qUA);  qUB = fma2(wiB[3], u1.y, qUB);         \
        qVA = fma2(w1A[3], v1.y, qVA);  qVB = fma2(w1B[3], v1.y, qVB);         \
        qUA = fma2(wiA[4], u2.x, qUA);  qUB = fma2(wiB[4], u2.x, qUB);         \
        qVA = fma2(w1A[4], v2.x, qVA);  qVB = fma2(w1B[4], v2.x, qVB);         \
        qUA = fma2(wiA[5], u2.y, qUA);  qUB = fma2(wiB[5], u2.y, qUB);         \
        qVA = fma2(w1A[5], v2.y, qVA);  qVB = fma2(w1B[5], v2.y, qVB);         \
        qUA = fma2(wiA[6], u3.x, qUA);  qUB = fma2(wiB[6], u3.x, qUB);         \
        qVA = fma2(w1A[6], v3.x, qVA);  qVB = fma2(w1B[6], v3.x, qVB);         \
        qUA = fma2(wiA[7], u3.y, qUA);  qUB = fma2(wiB[7], u3.y, qUB);         \
        qVA = fma2(w1A[7], v3.y, qVA);  qVB = fma2(w1B[7], v3.y, qVB);         \
        const unsigned long long paA = fma2(pA2, ONE2, pA);                    \
        const unsigned long long paB = fma2(pB2, ONE2, pB);                    \
        const unsigned long long qaA = fma2(qVA, ONE2, qUA);                   \
        const unsigned long long qaB = fma2(qVB, ONE2, qUB);                   \
        float paL, paH, pbL, pbH, qaL, qaH, qbL, qbH;                          \
        unpk2(paA, paL, paH); unpk2(paB, pbL, pbH);                            \
        unpk2(qaA, qaL, qaH); unpk2(qaB, qbL, qbH);                            \
        const float pAraw = fmaf(xv, wxA, paL + paH);                          \
        const float pBraw = fmaf(xv, wxB, pbL + pbH);                          \
        const float qAraw = qaL + qaH;                                         \
        const float qBraw = qbL + qbH;                                         \
        const float psA = fmaf(mA, tanhA(kA * pAraw), cA);                     \
        const float qsA = fmaf(mA, tanhA(kA * qAraw), cA);                     \
        const float psB = sigA(pBraw);                                         \
        const float qsB = sigA(qBraw);                                         \
        const float pgg = __shfl_xor_sync(0xffffffffu, psA, 16);               \
        const float qgg = __shfl_xor_sync(0xffffffffu, qsA, 16);               \
        const float poo = __shfl_xor_sync(0xffffffffu, psB, 16);               \
        const float qoo = __shfl_xor_sync(0xffffffffu, qsB, 16);               \
        c0v = fmaf(psB, c0v, psA * pgg);                                       \
        c1v = fmaf(qsB, c1v, qsA * qgg);                                       \
        h0v = poo * tanhA(c0v);                                                \
        h1v = qoo * tanhA(c1v);                                                \
        if (!half) {                                                           \
            (WB)[j]      = h0v;                                                \
            (WB)[16 + j] = h1v;                                                \
            *outp = h1v;                                                       \
        }                                                                      \
        outp += H;                                                             \
        xv = xnext;                                                            \
        __syncwarp();                                                          \
    }

    // supersteps s = 0 .. T-2 (2047 total): 1023 pairs + 1 final
    for (int s = 0; s < T - 3; s += 2) {
        SUPERSTEP(bufA, bufB, s)
        SUPERSTEP(bufB, bufA, s + 1)
    }
    SUPERSTEP(bufA, bufB, T - 2)

    // =================== tail: layer1 step T-1 (reads bufB) ================
    {
        const ulonglong2* hp0 = reinterpret_cast<const ulonglong2*>(bufB);
        const ulonglong2* hp1 = reinterpret_cast<const ulonglong2*>(bufB + 16);
        ulonglong2 u0 = hp0[0], u1 = hp0[1], u2 = hp0[2], u3 = hp0[3];
        ulonglong2 v0 = hp1[0], v1 = hp1[1], v2 = hp1[2], v3 = hp1[3];
        unsigned long long qUA = bias2A1, qUB = bias2B1;
        unsigned long long qVA = 0ull,   qVB = 0ull;
        qUA = fma2(wiA[0], u0.x, qUA);  qUB = fma2(wiB[0], u0.x, qUB);
        qVA = fma2(w1A[0], v0.x, qVA);  qVB = fma2(w1B[0], v0.x, qVB);
        qUA = fma2(wiA[1], u0.y, qUA);  qUB = fma2(wiB[1], u0.y, qUB);
        qVA = fma2(w1A[1], v0.y, qVA);  qVB = fma2(w1B[1], v0.y, qVB);
        qUA = fma2(wiA[2], u1.x, qUA);  qUB = fma2(wiB[2], u1.x, qUB);
        qVA = fma2(w1A[2], v1.x, qVA);  qVB = fma2(w1B[2], v1.x, qVB);
        qUA = fma2(wiA[3], u1.y, qUA);  qUB = fma2(wiB[3], u1.y, qUB);
        qVA = fma2(w1A[3], v1.y, qVA);  qVB = fma2(w1B[3], v1.y, qVB);
        qUA = fma2(wiA[4], u2.x, qUA);  qUB = fma2(wiB[4], u2.x, qUB);
        qVA = fma2(w1A[4], v2.x, qVA);  qVB = fma2(w1B[4], v2.x, qVB);
        qUA = fma2(wiA[5], u2.y, qUA);  qUB = fma2(wiB[5], u2.y, qUB);
        qVA = fma2(w1A[5], v2.y, qVA);  qVB = fma2(w1B[5], v2.y, qVB);
        qUA = fma2(wiA[6], u3.x, qUA);  qUB = fma2(wiB[6], u3.x, qUB);
        qVA = fma2(w1A[6], v3.x, qVA);  qVB = fma2(w1B[6], v3.x, qVB);
        qUA = fma2(wiA[7], u3.y, qUA);  qUB = fma2(wiB[7], u3.y, qUB);
        qVA = fma2(w1A[7], v3.y, qVA);  qVB = fma2(w1B[7], v3.y, qVB);
        const unsigned long long qaA = fma2(qVA, ONE2, qUA);
        const unsigned long long qaB = fma2(qVB, ONE2, qUB);
        float qaL, qaH, qbL, qbH;
        unpk2(qaA, qaL, qaH); unpk2(qaB, qbL, qbH);
        const float qAraw = qaL + qaH;
        const float qBraw = qbL + qbH;
        const float qsA = fmaf(mA, tanhA(kA * qAraw), cA);
        const float qsB = sigA(qBraw);
        const float qgg = __shfl_xor_sync(0xffffffffu, qsA, 16);
        const float qoo = __shfl_xor_sync(0xffffffffu, qsB, 16);
        c1v = fmaf(qsB, c1v, qsA * qgg);
        h1v = qoo * tanhA(c1v);
        if (!half) *outp = h1v;
    }

    // final states: hN [2,B,H] then cN [2,B,H] appended after out1 [B,T,H]
    if (!half) {
        float* hN = out + (size_t)B * T * H;
        float* cN = hN + 2 * B * H;
        hN[b * H + j]         = h0v;
        hN[B * H + b * H + j] = h1v;
        cN[b * H + j]         = c0v;
        cN[B * H + b * H + j] = c1v;
    }
}

extern "C" void kernel_launch(void* const* d_in, const int* in_sizes, int n_in,
                              void* d_out, int out_size) {
    const float* x    = (const float*)d_in[0];
    const float* h0   = (const float*)d_in[1];
    const float* c0   = (const float*)d_in[2];
    const float* Wih0 = (const float*)d_in[3];
    const float* Whh0 = (const float*)d_in[4];
    const float* bih0 = (const float*)d_in[5];
    const float* bhh0 = (const float*)d_in[6];
    const float* Wih1 = (const float*)d_in[7];
    const float* Whh1 = (const float*)d_in[8];
    const float* bih1 = (const float*)d_in[9];
    const float* bhh1 = (const float*)d_in[10];
    float* out = (float*)d_out;

    lstm2_kernel<<<B / 2, 64>>>(x, h0, c0, Wih0, Whh0, bih0, bhh0,
                                Wih1, Whh1, bih1, bhh1, out);
}